// round 15
// baseline (speedup 1.0000x reference)
#include <cuda_runtime.h>
#include <math.h>
#include <stdint.h>

// Problem constants
#define Bb 2
#define LL 2048
#define CC 512
#define HH 8
#define DD 64
#define BL (Bb * LL)   // 4096 rows per input

// Scratch: QKV in [B,H,L,D] per stream s and tensor t (0:Q,1:K,2:V),
// attention outputs in [B,L,C] per stream.
__device__ float g_qkv[2][3][Bb * HH * LL * DD];
__device__ float g_ao[2][BL * CC];

// ---------------------------------------------------------------------------
// helpers
// ---------------------------------------------------------------------------
__device__ __forceinline__ uint32_t f2tf(float f) {
    uint32_t u;
    asm("cvt.rna.tf32.f32 %0, %1;" : "=r"(u) : "f"(f));
    return u;
}

// round raw fp32 bits (from smem) to tf32 at fragment-load time
__device__ __forceinline__ uint32_t tfr(uint32_t raw) {
    uint32_t u;
    asm("cvt.rna.tf32.f32 %0, %1;" : "=r"(u) : "f"(__uint_as_float(raw)));
    return u;
}

__device__ __forceinline__ void mma_tf32(float c[4],
                                         uint32_t a0, uint32_t a1, uint32_t a2, uint32_t a3,
                                         uint32_t b0, uint32_t b1) {
    asm volatile(
        "mma.sync.aligned.m16n8k8.row.col.f32.tf32.tf32.f32 "
        "{%0,%1,%2,%3}, {%4,%5,%6,%7}, {%8,%9}, {%0,%1,%2,%3};"
        : "+f"(c[0]), "+f"(c[1]), "+f"(c[2]), "+f"(c[3])
        : "r"(a0), "r"(a1), "r"(a2), "r"(a3), "r"(b0), "r"(b1));
}

__device__ __forceinline__ uint32_t sptr(const void* p) {
    return (uint32_t)__cvta_generic_to_shared(p);
}
__device__ __forceinline__ void cp16(uint32_t dst, const void* src) {
    asm volatile("cp.async.cg.shared.global [%0], [%1], 16;" :: "r"(dst), "l"(src));
}
#define CP_COMMIT() asm volatile("cp.async.commit_group;")
#define CP_WAIT0()  asm volatile("cp.async.wait_group 0;")

// ---------------------------------------------------------------------------
// GEMM kernels (NT): Y[m,n] = sum_k A[m,k] * W[n,k] (+ bias)
// Block tile 128x128, 8 warps, warp tile 32x64, k-step 16.
// cp.async double-buffered; tf32 rounding at fragment load.
// ---------------------------------------------------------------------------
#define SA 20

// QKV projection: M=4096 per stream, N=1536, K=512. Scatters to g_qkv.
__global__ __launch_bounds__(256) void qkv_mma(
    const float* __restrict__ x1, const float* __restrict__ x2,
    const float* __restrict__ w, const float* __restrict__ bias)
{
    __shared__ uint32_t As[2][128 * SA];
    __shared__ uint32_t Bs[2][128 * SA];

    const int s  = blockIdx.z;
    const float* __restrict__ X = s ? x2 : x1;
    const int m0 = blockIdx.y * 128;
    const int n0 = blockIdx.x * 128;

    const int tid  = threadIdx.x;
    const int lane = tid & 31;
    const int wid  = tid >> 5;
    const int g = lane >> 2, t = lane & 3;
    const int wm = (wid >> 1) * 32;
    const int wn = (wid & 1) * 64;
    const int lr = tid >> 2;          // 0..63
    const int lc = (tid & 3) * 4;     // 0,4,8,12

    const float* __restrict__ Ag = X + (size_t)m0 * CC;
    const float* __restrict__ Bg = w + (size_t)n0 * CC;

    auto issue = [&](int b, int k0) {
        cp16(sptr(&As[b][lr * SA + lc]),        Ag + (size_t)lr * CC + k0 + lc);
        cp16(sptr(&As[b][(lr + 64) * SA + lc]), Ag + (size_t)(lr + 64) * CC + k0 + lc);
        cp16(sptr(&Bs[b][lr * SA + lc]),        Bg + (size_t)lr * CC + k0 + lc);
        cp16(sptr(&Bs[b][(lr + 64) * SA + lc]), Bg + (size_t)(lr + 64) * CC + k0 + lc);
    };

    float acc[2][8][4];
#pragma unroll
    for (int i = 0; i < 2; ++i)
#pragma unroll
        for (int j = 0; j < 8; ++j)
#pragma unroll
            for (int e = 0; e < 4; ++e) acc[i][j][e] = 0.f;

    issue(0, 0);
    CP_COMMIT();

    int buf = 0;
    for (int k0 = 0; k0 < CC; k0 += 16) {
        CP_WAIT0();
        __syncthreads();
        if (k0 + 16 < CC) {
            issue(buf ^ 1, k0 + 16);
            CP_COMMIT();
        }
#pragma unroll
        for (int kk = 0; kk < 2; ++kk) {
            uint32_t a[2][4];
#pragma unroll
            for (int mf = 0; mf < 2; ++mf) {
                const int row = wm + mf * 16;
                a[mf][0] = tfr(As[buf][(row + g) * SA + kk * 8 + t]);
                a[mf][1] = tfr(As[buf][(row + g + 8) * SA + kk * 8 + t]);
                a[mf][2] = tfr(As[buf][(row + g) * SA + kk * 8 + t + 4]);
                a[mf][3] = tfr(As[buf][(row + g + 8) * SA + kk * 8 + t + 4]);
            }
#pragma unroll
            for (int nf = 0; nf < 8; ++nf) {
                const int col = wn + nf * 8;
                uint32_t b0 = tfr(Bs[buf][(col + g) * SA + kk * 8 + t]);
                uint32_t b1 = tfr(Bs[buf][(col + g) * SA + kk * 8 + t + 4]);
                mma_tf32(acc[0][nf], a[0][0], a[0][1], a[0][2], a[0][3], b0, b1);
                mma_tf32(acc[1][nf], a[1][0], a[1][1], a[1][2], a[1][3], b0, b1);
            }
        }
        buf ^= 1;
    }

    // Epilogue: scatter into g_qkv
#pragma unroll
    for (int mf = 0; mf < 2; ++mf) {
        const int mA = m0 + wm + mf * 16 + g;
        const int mB = mA + 8;
#pragma unroll
        for (int nf = 0; nf < 8; ++nf) {
            const int f   = n0 + wn + nf * 8 + 2 * t;
            const int h   = f / 192;
            const int rem = f % 192;
            const int tsr = rem / 64;
            const int d   = rem & 63;
            const float bv0 = bias[f], bv1 = bias[f + 1];
            {
                const int bb = mA >> 11, l = mA & 2047;
                float2 v = make_float2(acc[mf][nf][0] + bv0, acc[mf][nf][1] + bv1);
                *(float2*)&g_qkv[s][tsr][(size_t)((bb * HH + h) * LL + l) * DD + d] = v;
            }
            {
                const int bb = mB >> 11, l = mB & 2047;
                float2 v = make_float2(acc[mf][nf][2] + bv0, acc[mf][nf][3] + bv1);
                *(float2*)&g_qkv[s][tsr][(size_t)((bb * HH + h) * LL + l) * DD + d] = v;
            }
        }
    }
}

// Output projection: M=8192, N=512, K=512. Reads g_ao, writes d_out.
__global__ __launch_bounds__(256) void proj_mma(
    const float* __restrict__ w, const float* __restrict__ bias,
    float* __restrict__ out)
{
    __shared__ uint32_t As[2][128 * SA];
    __shared__ uint32_t Bs[2][128 * SA];

    const int m0 = blockIdx.y * 128;
    const int n0 = blockIdx.x * 128;
    const float* __restrict__ A = &g_ao[0][0];

    const int tid  = threadIdx.x;
    const int lane = tid & 31;
    const int wid  = tid >> 5;
    const int g = lane >> 2, t = lane & 3;
    const int wm = (wid >> 1) * 32;
    const int wn = (wid & 1) * 64;
    const int lr = tid >> 2;
    const int lc = (tid & 3) * 4;

    const float* __restrict__ Ag = A + (size_t)m0 * CC;
    const float* __restrict__ Bg = w + (size_t)n0 * CC;

    auto issue = [&](int b, int k0) {
        cp16(sptr(&As[b][lr * SA + lc]),        Ag + (size_t)lr * CC + k0 + lc);
        cp16(sptr(&As[b][(lr + 64) * SA + lc]), Ag + (size_t)(lr + 64) * CC + k0 + lc);
        cp16(sptr(&Bs[b][lr * SA + lc]),        Bg + (size_t)lr * CC + k0 + lc);
        cp16(sptr(&Bs[b][(lr + 64) * SA + lc]), Bg + (size_t)(lr + 64) * CC + k0 + lc);
    };

    float acc[2][8][4];
#pragma unroll
    for (int i = 0; i < 2; ++i)
#pragma unroll
        for (int j = 0; j < 8; ++j)
#pragma unroll
            for (int e = 0; e < 4; ++e) acc[i][j][e] = 0.f;

    issue(0, 0);
    CP_COMMIT();

    int buf = 0;
    for (int k0 = 0; k0 < CC; k0 += 16) {
        CP_WAIT0();
        __syncthreads();
        if (k0 + 16 < CC) {
            issue(buf ^ 1, k0 + 16);
            CP_COMMIT();
        }
#pragma unroll
        for (int kk = 0; kk < 2; ++kk) {
            uint32_t a[2][4];
#pragma unroll
            for (int mf = 0; mf < 2; ++mf) {
                const int row = wm + mf * 16;
                a[mf][0] = tfr(As[buf][(row + g) * SA + kk * 8 + t]);
                a[mf][1] = tfr(As[buf][(row + g + 8) * SA + kk * 8 + t]);
                a[mf][2] = tfr(As[buf][(row + g) * SA + kk * 8 + t + 4]);
                a[mf][3] = tfr(As[buf][(row + g + 8) * SA + kk * 8 + t + 4]);
            }
#pragma unroll
            for (int nf = 0; nf < 8; ++nf) {
                const int col = wn + nf * 8;
                uint32_t b0 = tfr(Bs[buf][(col + g) * SA + kk * 8 + t]);
                uint32_t b1 = tfr(Bs[buf][(col + g) * SA + kk * 8 + t + 4]);
                mma_tf32(acc[0][nf], a[0][0], a[0][1], a[0][2], a[0][3], b0, b1);
                mma_tf32(acc[1][nf], a[1][0], a[1][1], a[1][2], a[1][3], b0, b1);
            }
        }
        buf ^= 1;
    }

#pragma unroll
    for (int mf = 0; mf < 2; ++mf) {
        const int mA = m0 + wm + mf * 16 + g;
        const int mB = mA + 8;
#pragma unroll
        for (int nf = 0; nf < 8; ++nf) {
            const int n = n0 + wn + nf * 8 + 2 * t;
            const float bv0 = bias[n], bv1 = bias[n + 1];
            float2 vA = make_float2(acc[mf][nf][0] + bv0, acc[mf][nf][1] + bv1);
            float2 vB = make_float2(acc[mf][nf][2] + bv0, acc[mf][nf][3] + bv1);
            *(float2*)&out[(size_t)mA * CC + n] = vA;
            *(float2*)&out[(size_t)mB * CC + n] = vB;
        }
    }
}

// ---------------------------------------------------------------------------
// Flash attention with tf32 mma + cp.async double-buffered K/V tiles.
// Block: 128 threads (4 warps), q-tile 64, kv-tile 64, D=64.
// Dynamic smem: KP[2] (K tile, reused for P) + Vs[2], stride 68.
// ---------------------------------------------------------------------------
#define SV 68
#define ATTN_SMEM (4 * 64 * SV * 4)   // 69632 bytes

__global__ __launch_bounds__(128) void attn_mma()
{
    extern __shared__ uint32_t smp[];
    uint32_t* KPb[2] = { smp,                smp + 64 * SV };
    uint32_t* Vsb[2] = { smp + 2 * 64 * SV,  smp + 3 * 64 * SV };

    const int s  = blockIdx.z;
    const int bh = blockIdx.y;
    const int q0 = blockIdx.x * 64;

    const float* __restrict__ Qg = &g_qkv[s][0][(size_t)bh * LL * DD];
    const float* __restrict__ Kg = &g_qkv[1 - s][1][(size_t)bh * LL * DD];
    const float* __restrict__ Vg = &g_qkv[1 - s][2][(size_t)bh * LL * DD];

    const int tid  = threadIdx.x;
    const int lane = tid & 31;
    const int wid  = tid >> 5;
    const int g = lane >> 2, t = lane & 3;
    const int wr = wid * 16;

    const int lrr = tid >> 1;          // 0..63 (row)
    const int lh  = tid & 1;           // column half selector

    // Issue tile 0 (K,V) into buffer 0 — overlaps with Q staging below.
    {
        const float* kr = Kg + (size_t)lrr * DD;
        const float* vr = Vg + (size_t)lrr * DD;
#pragma unroll
        for (int j = 0; j < 8; ++j) {
            const int c4 = (lh + 2 * j) * 4;
            cp16(sptr(&KPb[0][lrr * SV + c4]), kr + c4);
            cp16(sptr(&Vsb[0][lrr * SV + c4]), vr + c4);
        }
        CP_COMMIT();
    }

    // Stage Q (prescaled, tf32-rounded) into KPb[1]; pull fragments to regs.
#pragma unroll
    for (int j = 0; j < 8; ++j) {
        const int c4 = (lh + 2 * j) * 4;
        float4 q = *(const float4*)(Qg + (size_t)(q0 + lrr) * DD + c4);
        uint4 u;
        u.x = f2tf(q.x * 0.125f); u.y = f2tf(q.y * 0.125f);
        u.z = f2tf(q.z * 0.125f); u.w = f2tf(q.w * 0.125f);
        *(uint4*)&KPb[1][lrr * SV + c4] = u;
    }
    __syncthreads();

    uint32_t qa[8][4];
#pragma unroll
    for (int kk = 0; kk < 8; ++kk) {
        qa[kk][0] = KPb[1][(wr + g) * SV + kk * 8 + t];
        qa[kk][1] = KPb[1][(wr + g + 8) * SV + kk * 8 + t];
        qa[kk][2] = KPb[1][(wr + g) * SV + kk * 8 + t + 4];
        qa[kk][3] = KPb[1][(wr + g + 8) * SV + kk * 8 + t + 4];
    }

    float o[8][4];
#pragma unroll
    for (int nf = 0; nf < 8; ++nf)
#pragma unroll
        for (int e = 0; e < 4; ++e) o[nf][e] = 0.f;
    float mrow0 = -INFINITY, mrow1 = -INFINITY;
    float lrow0 = 0.f, lrow1 = 0.f;

    int buf = 0;
    for (int it = 0; it < LL / 64; ++it) {
        CP_WAIT0();
        __syncthreads();   // tile `it` landed; everyone past previous iter

        // Prefetch tile it+1 into the other buffer (overlaps compute below)
        if (it + 1 < LL / 64) {
            const float* kr = Kg + (size_t)((it + 1) * 64 + lrr) * DD;
            const float* vr = Vg + (size_t)((it + 1) * 64 + lrr) * DD;
            const int nb = buf ^ 1;
#pragma unroll
            for (int j = 0; j < 8; ++j) {
                const int c4 = (lh + 2 * j) * 4;
                cp16(sptr(&KPb[nb][lrr * SV + c4]), kr + c4);
                cp16(sptr(&Vsb[nb][lrr * SV + c4]), vr + c4);
            }
            CP_COMMIT();
        }

        const uint32_t* __restrict__ KP = KPb[buf];
        const uint32_t* __restrict__ Vs = Vsb[buf];

        // S = Q @ K^T  (warp: 16 x 64); round K at fragment load
        float sc[8][4];
#pragma unroll
        for (int nf = 0; nf < 8; ++nf)
#pragma unroll
            for (int e = 0; e < 4; ++e) sc[nf][e] = 0.f;
#pragma unroll
        for (int nf = 0; nf < 8; ++nf) {
#pragma unroll
            for (int kk = 0; kk < 8; ++kk) {
                uint32_t b0 = tfr(KP[(nf * 8 + g) * SV + kk * 8 + t]);
                uint32_t b1 = tfr(KP[(nf * 8 + g) * SV + kk * 8 + t + 4]);
                mma_tf32(sc[nf], qa[kk][0], qa[kk][1], qa[kk][2], qa[kk][3], b0, b1);
            }
        }

        // Online softmax
        float mx0 = -INFINITY, mx1 = -INFINITY;
#pragma unroll
        for (int nf = 0; nf < 8; ++nf) {
            mx0 = fmaxf(mx0, fmaxf(sc[nf][0], sc[nf][1]));
            mx1 = fmaxf(mx1, fmaxf(sc[nf][2], sc[nf][3]));
        }
        mx0 = fmaxf(mx0, __shfl_xor_sync(0xffffffffu, mx0, 1));
        mx0 = fmaxf(mx0, __shfl_xor_sync(0xffffffffu, mx0, 2));
        mx1 = fmaxf(mx1, __shfl_xor_sync(0xffffffffu, mx1, 1));
        mx1 = fmaxf(mx1, __shfl_xor_sync(0xffffffffu, mx1, 2));

        const float mn0 = fmaxf(mrow0, mx0);
        const float mn1 = fmaxf(mrow1, mx1);
        const float corr0 = __expf(mrow0 - mn0);
        const float corr1 = __expf(mrow1 - mn1);
        mrow0 = mn0; mrow1 = mn1;

        float ls0 = 0.f, ls1 = 0.f;
#pragma unroll
        for (int nf = 0; nf < 8; ++nf) {
            sc[nf][0] = __expf(sc[nf][0] - mn0); ls0 += sc[nf][0];
            sc[nf][1] = __expf(sc[nf][1] - mn0); ls0 += sc[nf][1];
            sc[nf][2] = __expf(sc[nf][2] - mn1); ls1 += sc[nf][2];
            sc[nf][3] = __expf(sc[nf][3] - mn1); ls1 += sc[nf][3];
        }
        ls0 += __shfl_xor_sync(0xffffffffu, ls0, 1);
        ls0 += __shfl_xor_sync(0xffffffffu, ls0, 2);
        ls1 += __shfl_xor_sync(0xffffffffu, ls1, 1);
        ls1 += __shfl_xor_sync(0xffffffffu, ls1, 2);
        lrow0 = lrow0 * corr0 + ls0;
        lrow1 = lrow1 * corr1 + ls1;
#pragma unroll
        for (int nf = 0; nf < 8; ++nf) {
            o[nf][0] *= corr0; o[nf][1] *= corr0;
            o[nf][2] *= corr1; o[nf][3] *= corr1;
        }

        __syncthreads();   // all warps done reading KP as K

        // Store P (tf32) into KP rows of this warp
        uint32_t* KPw = KPb[buf];
#pragma unroll
        for (int nf = 0; nf < 8; ++nf) {
            uint2 uA, uB;
            uA.x = f2tf(sc[nf][0]); uA.y = f2tf(sc[nf][1]);
            uB.x = f2tf(sc[nf][2]); uB.y = f2tf(sc[nf][3]);
            *(uint2*)&KPw[(wr + g) * SV + nf * 8 + 2 * t] = uA;
            *(uint2*)&KPw[(wr + g + 8) * SV + nf * 8 + 2 * t] = uB;
        }
        __syncwarp();

        // O += P @ V  (P already tf32; round V at fragment load)
#pragma unroll
        for (int kk = 0; kk < 8; ++kk) {
            uint32_t p0 = KPw[(wr + g) * SV + kk * 8 + t];
            uint32_t p1 = KPw[(wr + g + 8) * SV + kk * 8 + t];
            uint32_t p2 = KPw[(wr + g) * SV + kk * 8 + t + 4];
            uint32_t p3 = KPw[(wr + g + 8) * SV + kk * 8 + t + 4];
#pragma unroll
            for (int nf = 0; nf < 8; ++nf) {
                uint32_t b0 = tfr(Vs[(kk * 8 + t) * SV + nf * 8 + g]);
                uint32_t b1 = tfr(Vs[(kk * 8 + t + 4) * SV + nf * 8 + g]);
                mma_tf32(o[nf], p0, p1, p2, p3, b0, b1);
            }
        }
        buf ^= 1;
        // next iteration's top barrier protects this buffer before reuse
    }

    // Epilogue: normalize, write to g_ao[s] in [B, L, H*D]
    const int bb = bh >> 3;
    const int h  = bh & 7;
    const float inv0 = 1.f / lrow0;
    const float inv1 = 1.f / lrow1;
    const int rowA = q0 + wr + g;
    const int rowB = rowA + 8;
    float* __restrict__ ao = &g_ao[s][0];
#pragma unroll
    for (int nf = 0; nf < 8; ++nf) {
        const int col = h * DD + nf * 8 + 2 * t;
        float2 vA = make_float2(o[nf][0] * inv0, o[nf][1] * inv0);
        float2 vB = make_float2(o[nf][2] * inv1, o[nf][3] * inv1);
        *(float2*)&ao[(size_t)(bb * LL + rowA) * CC + col] = vA;
        *(float2*)&ao[(size_t)(bb * LL + rowB) * CC + col] = vB;
    }
}

// ---------------------------------------------------------------------------
extern "C" void kernel_launch(void* const* d_in, const int* in_sizes, int n_in,
                              void* d_out, int out_size)
{
    const float* x1    = (const float*)d_in[0];
    const float* x2    = (const float*)d_in[1];
    const float* qkv_w = (const float*)d_in[2];
    const float* qkv_b = (const float*)d_in[3];
    const float* out_w = (const float*)d_in[4];
    const float* out_b = (const float*)d_in[5];
    float* out = (float*)d_out;

    // idempotent; legal during graph capture (not a stream op)
    cudaFuncSetAttribute(attn_mma, cudaFuncAttributeMaxDynamicSharedMemorySize,
                         ATTN_SMEM);

    // Stage 1: QKV projections (both inputs)
    qkv_mma<<<dim3(1536 / 128, BL / 128, 2), 256>>>(x1, x2, qkv_w, qkv_b);

    // Stage 2: cross attention (both directions)
    attn_mma<<<dim3(LL / 64, Bb * HH, 2), 128, ATTN_SMEM>>>();

    // Stage 3: output projection -> d_out (out1 then out2)
    proj_mma<<<dim3(CC / 128, 2 * BL / 128), 256>>>(out_w, out_b, out);
}

// round 17
// speedup vs baseline: 1.0641x; 1.0641x over previous
#include <cuda_runtime.h>
#include <math.h>
#include <stdint.h>

// Problem constants
#define Bb 2
#define LL 2048
#define CC 512
#define HH 8
#define DD 64
#define BL (Bb * LL)   // 4096 rows per input

// Scratch (device globals; no allocation allowed):
// g_qkv: tf32-pre-rounded Q(prescaled)/K/V in [B,H,L,D], per stream.
// g_ao:  tf32-pre-rounded attention outputs [B,L,C] per stream.
// g_xr:  tf32-rounded copies of x1,x2.
// g_wq / g_wo: tf32-rounded weights.
__device__ float g_qkv[2][3][Bb * HH * LL * DD];
__device__ float g_ao[2][BL * CC];
__device__ float g_xr[2][BL * CC];
__device__ float g_wq[3 * CC * CC];
__device__ float g_wo[CC * CC];

// ---------------------------------------------------------------------------
// helpers
// ---------------------------------------------------------------------------
__device__ __forceinline__ uint32_t f2tf(float f) {
    uint32_t u;
    asm("cvt.rna.tf32.f32 %0, %1;" : "=r"(u) : "f"(f));
    return u;
}
__device__ __forceinline__ float f2tff(float f) {
    return __uint_as_float(f2tf(f));
}

__device__ __forceinline__ void mma_tf32(float c[4],
                                         uint32_t a0, uint32_t a1, uint32_t a2, uint32_t a3,
                                         uint32_t b0, uint32_t b1) {
    asm volatile(
        "mma.sync.aligned.m16n8k8.row.col.f32.tf32.tf32.f32 "
        "{%0,%1,%2,%3}, {%4,%5,%6,%7}, {%8,%9}, {%0,%1,%2,%3};"
        : "+f"(c[0]), "+f"(c[1]), "+f"(c[2]), "+f"(c[3])
        : "r"(a0), "r"(a1), "r"(a2), "r"(a3), "r"(b0), "r"(b1));
}

__device__ __forceinline__ uint32_t sptr(const void* p) {
    return (uint32_t)__cvta_generic_to_shared(p);
}
__device__ __forceinline__ void cp16(uint32_t dst, const void* src) {
    asm volatile("cp.async.cg.shared.global [%0], [%1], 16;" :: "r"(dst), "l"(src));
}
#define CP_COMMIT() asm volatile("cp.async.commit_group;")
#define CP_WAIT0()  asm volatile("cp.async.wait_group 0;")

// ---------------------------------------------------------------------------
// Prep: tf32-round x1, x2, qkv_w, out_w into scratch. One float4 per thread.
// ---------------------------------------------------------------------------
#define NX4   (BL * CC / 4)            // 524288 per x tensor
#define NWQ4  (3 * CC * CC / 4)        // 196608
#define NWO4  (CC * CC / 4)            // 65536
#define NPREP (2 * NX4 + NWQ4 + NWO4)  // 1310720

__global__ __launch_bounds__(256) void prep_round(
    const float* __restrict__ x1, const float* __restrict__ x2,
    const float* __restrict__ qw, const float* __restrict__ ow)
{
    int i = blockIdx.x * blockDim.x + threadIdx.x;
    if (i >= NPREP) return;
    const float* src;
    float* dst;
    if (i < NX4)                { src = x1; dst = &g_xr[0][0]; }
    else if (i < 2 * NX4)       { src = x2; dst = &g_xr[1][0]; i -= NX4; }
    else if (i < 2 * NX4 + NWQ4){ src = qw; dst = g_wq;        i -= 2 * NX4; }
    else                        { src = ow; dst = g_wo;        i -= 2 * NX4 + NWQ4; }
    float4 v = *(const float4*)(src + (size_t)i * 4);
    v.x = f2tff(v.x); v.y = f2tff(v.y); v.z = f2tff(v.z); v.w = f2tff(v.w);
    *(float4*)(dst + (size_t)i * 4) = v;
}

// ---------------------------------------------------------------------------
// GEMM kernels (NT): Y[m,n] = sum_k A[m,k] * W[n,k] (+ bias)
// Block tile 128x128, 8 warps, warp tile 32x64, k-step 16.
// cp.async double-buffered; operands are pre-rounded tf32 -> no mainloop cvt.
// ---------------------------------------------------------------------------
#define SA 20

// QKV projection: M=4096 per stream, N=1536, K=512. Scatters to g_qkv.
__global__ __launch_bounds__(256) void qkv_mma(const float* __restrict__ bias)
{
    __shared__ uint32_t As[2][128 * SA];
    __shared__ uint32_t Bs[2][128 * SA];

    const int s  = blockIdx.z;
    const int m0 = blockIdx.y * 128;
    const int n0 = blockIdx.x * 128;

    const int tid  = threadIdx.x;
    const int lane = tid & 31;
    const int wid  = tid >> 5;
    const int g = lane >> 2, t = lane & 3;
    const int wm = (wid >> 1) * 32;
    const int wn = (wid & 1) * 64;
    const int lr = tid >> 2;          // 0..63
    const int lc = (tid & 3) * 4;     // 0,4,8,12

    const float* __restrict__ Ag = &g_xr[s][0] + (size_t)m0 * CC;
    const float* __restrict__ Bg = g_wq + (size_t)n0 * CC;

    auto issue = [&](int b, int k0) {
        cp16(sptr(&As[b][lr * SA + lc]),        Ag + (size_t)lr * CC + k0 + lc);
        cp16(sptr(&As[b][(lr + 64) * SA + lc]), Ag + (size_t)(lr + 64) * CC + k0 + lc);
        cp16(sptr(&Bs[b][lr * SA + lc]),        Bg + (size_t)lr * CC + k0 + lc);
        cp16(sptr(&Bs[b][(lr + 64) * SA + lc]), Bg + (size_t)(lr + 64) * CC + k0 + lc);
    };

    float acc[2][8][4];
#pragma unroll
    for (int i = 0; i < 2; ++i)
#pragma unroll
        for (int j = 0; j < 8; ++j)
#pragma unroll
            for (int e = 0; e < 4; ++e) acc[i][j][e] = 0.f;

    issue(0, 0);
    CP_COMMIT();

    int buf = 0;
    for (int k0 = 0; k0 < CC; k0 += 16) {
        CP_WAIT0();
        __syncthreads();
        if (k0 + 16 < CC) {
            issue(buf ^ 1, k0 + 16);
            CP_COMMIT();
        }
#pragma unroll
        for (int kk = 0; kk < 2; ++kk) {
            uint32_t a[2][4];
#pragma unroll
            for (int mf = 0; mf < 2; ++mf) {
                const int row = wm + mf * 16;
                a[mf][0] = As[buf][(row + g) * SA + kk * 8 + t];
                a[mf][1] = As[buf][(row + g + 8) * SA + kk * 8 + t];
                a[mf][2] = As[buf][(row + g) * SA + kk * 8 + t + 4];
                a[mf][3] = As[buf][(row + g + 8) * SA + kk * 8 + t + 4];
            }
#pragma unroll
            for (int nf = 0; nf < 8; ++nf) {
                const int col = wn + nf * 8;
                uint32_t b0 = Bs[buf][(col + g) * SA + kk * 8 + t];
                uint32_t b1 = Bs[buf][(col + g) * SA + kk * 8 + t + 4];
                mma_tf32(acc[0][nf], a[0][0], a[0][1], a[0][2], a[0][3], b0, b1);
                mma_tf32(acc[1][nf], a[1][0], a[1][1], a[1][2], a[1][3], b0, b1);
            }
        }
        buf ^= 1;
    }

    // Epilogue: add bias, scale Q by 1/8, tf32-round, scatter into g_qkv
#pragma unroll
    for (int mf = 0; mf < 2; ++mf) {
        const int mA = m0 + wm + mf * 16 + g;
        const int mB = mA + 8;
#pragma unroll
        for (int nf = 0; nf < 8; ++nf) {
            const int f   = n0 + wn + nf * 8 + 2 * t;
            const int h   = f / 192;
            const int rem = f % 192;
            const int tsr = rem / 64;
            const int d   = rem & 63;
            const float qs = (tsr == 0) ? 0.125f : 1.0f;
            const float bv0 = bias[f], bv1 = bias[f + 1];
            {
                const int bb = mA >> 11, l = mA & 2047;
                float2 v = make_float2(f2tff((acc[mf][nf][0] + bv0) * qs),
                                       f2tff((acc[mf][nf][1] + bv1) * qs));
                *(float2*)&g_qkv[s][tsr][(size_t)((bb * HH + h) * LL + l) * DD + d] = v;
            }
            {
                const int bb = mB >> 11, l = mB & 2047;
                float2 v = make_float2(f2tff((acc[mf][nf][2] + bv0) * qs),
                                       f2tff((acc[mf][nf][3] + bv1) * qs));
                *(float2*)&g_qkv[s][tsr][(size_t)((bb * HH + h) * LL + l) * DD + d] = v;
            }
        }
    }
}

// Output projection: M=8192, N=512, K=512. Reads g_ao (pre-rounded), writes d_out.
__global__ __launch_bounds__(256) void proj_mma(
    const float* __restrict__ bias, float* __restrict__ out)
{
    __shared__ uint32_t As[2][128 * SA];
    __shared__ uint32_t Bs[2][128 * SA];

    const int m0 = blockIdx.y * 128;
    const int n0 = blockIdx.x * 128;

    const int tid  = threadIdx.x;
    const int lane = tid & 31;
    const int wid  = tid >> 5;
    const int g = lane >> 2, t = lane & 3;
    const int wm = (wid >> 1) * 32;
    const int wn = (wid & 1) * 64;
    const int lr = tid >> 2;
    const int lc = (tid & 3) * 4;

    const float* __restrict__ Ag = &g_ao[0][0] + (size_t)m0 * CC;
    const float* __restrict__ Bg = g_wo + (size_t)n0 * CC;

    auto issue = [&](int b, int k0) {
        cp16(sptr(&As[b][lr * SA + lc]),        Ag + (size_t)lr * CC + k0 + lc);
        cp16(sptr(&As[b][(lr + 64) * SA + lc]), Ag + (size_t)(lr + 64) * CC + k0 + lc);
        cp16(sptr(&Bs[b][lr * SA + lc]),        Bg + (size_t)lr * CC + k0 + lc);
        cp16(sptr(&Bs[b][(lr + 64) * SA + lc]), Bg + (size_t)(lr + 64) * CC + k0 + lc);
    };

    float acc[2][8][4];
#pragma unroll
    for (int i = 0; i < 2; ++i)
#pragma unroll
        for (int j = 0; j < 8; ++j)
#pragma unroll
            for (int e = 0; e < 4; ++e) acc[i][j][e] = 0.f;

    issue(0, 0);
    CP_COMMIT();

    int buf = 0;
    for (int k0 = 0; k0 < CC; k0 += 16) {
        CP_WAIT0();
        __syncthreads();
        if (k0 + 16 < CC) {
            issue(buf ^ 1, k0 + 16);
            CP_COMMIT();
        }
#pragma unroll
        for (int kk = 0; kk < 2; ++kk) {
            uint32_t a[2][4];
#pragma unroll
            for (int mf = 0; mf < 2; ++mf) {
                const int row = wm + mf * 16;
                a[mf][0] = As[buf][(row + g) * SA + kk * 8 + t];
                a[mf][1] = As[buf][(row + g + 8) * SA + kk * 8 + t];
                a[mf][2] = As[buf][(row + g) * SA + kk * 8 + t + 4];
                a[mf][3] = As[buf][(row + g + 8) * SA + kk * 8 + t + 4];
            }
#pragma unroll
            for (int nf = 0; nf < 8; ++nf) {
                const int col = wn + nf * 8;
                uint32_t b0 = Bs[buf][(col + g) * SA + kk * 8 + t];
                uint32_t b1 = Bs[buf][(col + g) * SA + kk * 8 + t + 4];
                mma_tf32(acc[0][nf], a[0][0], a[0][1], a[0][2], a[0][3], b0, b1);
                mma_tf32(acc[1][nf], a[1][0], a[1][1], a[1][2], a[1][3], b0, b1);
            }
        }
        buf ^= 1;
    }

#pragma unroll
    for (int mf = 0; mf < 2; ++mf) {
        const int mA = m0 + wm + mf * 16 + g;
        const int mB = mA + 8;
#pragma unroll
        for (int nf = 0; nf < 8; ++nf) {
            const int n = n0 + wn + nf * 8 + 2 * t;
            const float bv0 = bias[n], bv1 = bias[n + 1];
            float2 vA = make_float2(acc[mf][nf][0] + bv0, acc[mf][nf][1] + bv1);
            float2 vB = make_float2(acc[mf][nf][2] + bv0, acc[mf][nf][3] + bv1);
            *(float2*)&out[(size_t)mA * CC + n] = vA;
            *(float2*)&out[(size_t)mB * CC + n] = vB;
        }
    }
}

// ---------------------------------------------------------------------------
// Flash attention, tf32 mma, cp.async double-buffered K/V. All operands
// pre-rounded tf32 in gmem -> no cvt in mainloop except P after softmax.
// Block: 128 threads (4 warps), q-tile 64, kv-tile 64, D=64.
// ---------------------------------------------------------------------------
#define SV 68
#define ATTN_SMEM (4 * 64 * SV * 4)   // 69632 bytes

__global__ __launch_bounds__(128) void attn_mma()
{
    extern __shared__ uint32_t smp[];
    uint32_t* KPb[2] = { smp,                smp + 64 * SV };
    uint32_t* Vsb[2] = { smp + 2 * 64 * SV,  smp + 3 * 64 * SV };

    const int s  = blockIdx.z;
    const int bh = blockIdx.y;
    const int q0 = blockIdx.x * 64;

    const float* __restrict__ Qg = &g_qkv[s][0][(size_t)bh * LL * DD];
    const float* __restrict__ Kg = &g_qkv[1 - s][1][(size_t)bh * LL * DD];
    const float* __restrict__ Vg = &g_qkv[1 - s][2][(size_t)bh * LL * DD];

    const int tid  = threadIdx.x;
    const int lane = tid & 31;
    const int wid  = tid >> 5;
    const int g = lane >> 2, t = lane & 3;
    const int wr = wid * 16;

    const int lrr = tid >> 1;          // 0..63 (row)
    const int lh  = tid & 1;           // column half selector

    // Prologue: cp.async tile0 K/V into buf0 AND Q tile into KPb[1].
    {
        const float* kr = Kg + (size_t)lrr * DD;
        const float* vr = Vg + (size_t)lrr * DD;
        const float* qr = Qg + (size_t)(q0 + lrr) * DD;
#pragma unroll
        for (int j = 0; j < 8; ++j) {
            const int c4 = (lh + 2 * j) * 4;
            cp16(sptr(&KPb[0][lrr * SV + c4]), kr + c4);
            cp16(sptr(&Vsb[0][lrr * SV + c4]), vr + c4);
            cp16(sptr(&KPb[1][lrr * SV + c4]), qr + c4);
        }
        CP_COMMIT();
    }
    CP_WAIT0();
    __syncthreads();

    // Q fragments (already prescaled + tf32-rounded by qkv epilogue)
    uint32_t qa[8][4];
#pragma unroll
    for (int kk = 0; kk < 8; ++kk) {
        qa[kk][0] = KPb[1][(wr + g) * SV + kk * 8 + t];
        qa[kk][1] = KPb[1][(wr + g + 8) * SV + kk * 8 + t];
        qa[kk][2] = KPb[1][(wr + g) * SV + kk * 8 + t + 4];
        qa[kk][3] = KPb[1][(wr + g + 8) * SV + kk * 8 + t + 4];
    }

    float o[8][4];
#pragma unroll
    for (int nf = 0; nf < 8; ++nf)
#pragma unroll
        for (int e = 0; e < 4; ++e) o[nf][e] = 0.f;
    float mrow0 = -INFINITY, mrow1 = -INFINITY;
    float lrow0 = 0.f, lrow1 = 0.f;

    int buf = 0;
    for (int it = 0; it < LL / 64; ++it) {
        CP_WAIT0();
        __syncthreads();   // tile `it` landed; qa reads done; prev iter done

        // Prefetch tile it+1 into the other buffer (overlaps compute below)
        if (it + 1 < LL / 64) {
            const float* kr = Kg + (size_t)((it + 1) * 64 + lrr) * DD;
            const float* vr = Vg + (size_t)((it + 1) * 64 + lrr) * DD;
            const int nb = buf ^ 1;
#pragma unroll
            for (int j = 0; j < 8; ++j) {
                const int c4 = (lh + 2 * j) * 4;
                cp16(sptr(&KPb[nb][lrr * SV + c4]), kr + c4);
                cp16(sptr(&Vsb[nb][lrr * SV + c4]), vr + c4);
            }
            CP_COMMIT();
        }

        const uint32_t* __restrict__ KP = KPb[buf];
        const uint32_t* __restrict__ Vs = Vsb[buf];

        // S = Q @ K^T  (warp: 16 x 64); K already tf32
        float sc[8][4];
#pragma unroll
        for (int nf = 0; nf < 8; ++nf)
#pragma unroll
            for (int e = 0; e < 4; ++e) sc[nf][e] = 0.f;
#pragma unroll
        for (int nf = 0; nf < 8; ++nf) {
#pragma unroll
            for (int kk = 0; kk < 8; ++kk) {
                uint32_t b0 = KP[(nf * 8 + g) * SV + kk * 8 + t];
                uint32_t b1 = KP[(nf * 8 + g) * SV + kk * 8 + t + 4];
                mma_tf32(sc[nf], qa[kk][0], qa[kk][1], qa[kk][2], qa[kk][3], b0, b1);
            }
        }

        // Online softmax
        float mx0 = -INFINITY, mx1 = -INFINITY;
#pragma unroll
        for (int nf = 0; nf < 8; ++nf) {
            mx0 = fmaxf(mx0, fmaxf(sc[nf][0], sc[nf][1]));
            mx1 = fmaxf(mx1, fmaxf(sc[nf][2], sc[nf][3]));
        }
        mx0 = fmaxf(mx0, __shfl_xor_sync(0xffffffffu, mx0, 1));
        mx0 = fmaxf(mx0, __shfl_xor_sync(0xffffffffu, mx0, 2));
        mx1 = fmaxf(mx1, __shfl_xor_sync(0xffffffffu, mx1, 1));
        mx1 = fmaxf(mx1, __shfl_xor_sync(0xffffffffu, mx1, 2));

        const float mn0 = fmaxf(mrow0, mx0);
        const float mn1 = fmaxf(mrow1, mx1);
        const float corr0 = __expf(mrow0 - mn0);
        const float corr1 = __expf(mrow1 - mn1);
        mrow0 = mn0; mrow1 = mn1;

        float ls0 = 0.f, ls1 = 0.f;
#pragma unroll
        for (int nf = 0; nf < 8; ++nf) {
            sc[nf][0] = __expf(sc[nf][0] - mn0); ls0 += sc[nf][0];
            sc[nf][1] = __expf(sc[nf][1] - mn0); ls0 += sc[nf][1];
            sc[nf][2] = __expf(sc[nf][2] - mn1); ls1 += sc[nf][2];
            sc[nf][3] = __expf(sc[nf][3] - mn1); ls1 += sc[nf][3];
        }
        ls0 += __shfl_xor_sync(0xffffffffu, ls0, 1);
        ls0 += __shfl_xor_sync(0xffffffffu, ls0, 2);
        ls1 += __shfl_xor_sync(0xffffffffu, ls1, 1);
        ls1 += __shfl_xor_sync(0xffffffffu, ls1, 2);
        lrow0 = lrow0 * corr0 + ls0;
        lrow1 = lrow1 * corr1 + ls1;
#pragma unroll
        for (int nf = 0; nf < 8; ++nf) {
            o[nf][0] *= corr0; o[nf][1] *= corr0;
            o[nf][2] *= corr1; o[nf][3] *= corr1;
        }

        __syncthreads();   // all warps done reading KP as K

        // Store P (tf32) into KP rows of this warp
        uint32_t* KPw = KPb[buf];
#pragma unroll
        for (int nf = 0; nf < 8; ++nf) {
            uint2 uA, uB;
            uA.x = f2tf(sc[nf][0]); uA.y = f2tf(sc[nf][1]);
            uB.x = f2tf(sc[nf][2]); uB.y = f2tf(sc[nf][3]);
            *(uint2*)&KPw[(wr + g) * SV + nf * 8 + 2 * t] = uA;
            *(uint2*)&KPw[(wr + g + 8) * SV + nf * 8 + 2 * t] = uB;
        }
        __syncwarp();

        // O += P @ V   (V already tf32)
#pragma unroll
        for (int kk = 0; kk < 8; ++kk) {
            uint32_t p0 = KPw[(wr + g) * SV + kk * 8 + t];
            uint32_t p1 = KPw[(wr + g + 8) * SV + kk * 8 + t];
            uint32_t p2 = KPw[(wr + g) * SV + kk * 8 + t + 4];
            uint32_t p3 = KPw[(wr + g + 8) * SV + kk * 8 + t + 4];
#pragma unroll
            for (int nf = 0; nf < 8; ++nf) {
                uint32_t b0 = Vs[(kk * 8 + t) * SV + nf * 8 + g];
                uint32_t b1 = Vs[(kk * 8 + t + 4) * SV + nf * 8 + g];
                mma_tf32(o[nf], p0, p1, p2, p3, b0, b1);
            }
        }
        buf ^= 1;
    }

    // Epilogue: normalize, tf32-round, write to g_ao[s] in [B, L, H*D]
    const int bb = bh >> 3;
    const int h  = bh & 7;
    const float inv0 = 1.f / lrow0;
    const float inv1 = 1.f / lrow1;
    const int rowA = q0 + wr + g;
    const int rowB = rowA + 8;
    float* __restrict__ ao = &g_ao[s][0];
#pragma unroll
    for (int nf = 0; nf < 8; ++nf) {
        const int col = h * DD + nf * 8 + 2 * t;
        float2 vA = make_float2(f2tff(o[nf][0] * inv0), f2tff(o[nf][1] * inv0));
        float2 vB = make_float2(f2tff(o[nf][2] * inv1), f2tff(o[nf][3] * inv1));
        *(float2*)&ao[(size_t)(bb * LL + rowA) * CC + col] = vA;
        *(float2*)&ao[(size_t)(bb * LL + rowB) * CC + col] = vB;
    }
}

// ---------------------------------------------------------------------------
extern "C" void kernel_launch(void* const* d_in, const int* in_sizes, int n_in,
                              void* d_out, int out_size)
{
    const float* x1    = (const float*)d_in[0];
    const float* x2    = (const float*)d_in[1];
    const float* qkv_w = (const float*)d_in[2];
    const float* qkv_b = (const float*)d_in[3];
    const float* out_w = (const float*)d_in[4];
    const float* out_b = (const float*)d_in[5];
    float* out = (float*)d_out;

    // idempotent; legal during graph capture (not a stream op)
    cudaFuncSetAttribute(attn_mma, cudaFuncAttributeMaxDynamicSharedMemorySize,
                         ATTN_SMEM);

    // Stage 0: tf32-round inputs & weights into scratch
    prep_round<<<(NPREP + 255) / 256, 256>>>(x1, x2, qkv_w, out_w);

    // Stage 1: QKV projections (both inputs)
    qkv_mma<<<dim3(1536 / 128, BL / 128, 2), 256>>>(qkv_b);

    // Stage 2: cross attention (both directions)
    attn_mma<<<dim3(LL / 64, Bb * HH, 2), 128, ATTN_SMEM>>>();

    // Stage 3: output projection -> d_out (out1 then out2)
    proj_mma<<<dim3(CC / 128, 2 * BL / 128), 256>>>(out_b, out);
}